// round 10
// baseline (speedup 1.0000x reference)
#include <cuda_runtime.h>
#include <cstdint>

#define N_NODES 50000
#define N_EDGES 800000
#define IN_DIM  128
#define OUT_DIM 128
#define EDGE_DIM 64

#define ETILE     64                       // edges per tile
#define TPB_TILES 20                       // tiles per block
#define EGRID_X   625                      // 625*20*64 = 800000
// dynamic smem layout (bytes)
#define SM_WP     0                        // Wp[32 kp][64 o] u64 = 16384
#define SM_E      16384                    // Esh[2][64 edge][64 k] f32 = 2*16384
#define SM_TOTAL  49152

typedef unsigned long long u64;

__device__ __align__(16) float g_HU[(size_t)N_NODES * OUT_DIM];
__device__ __align__(16) float g_HW[(size_t)N_NODES * OUT_DIM];
__device__ int g_idx_is64;

__device__ __forceinline__ u64 pack2(float lo, float hi) {
    u64 r; asm("mov.b64 %0, {%1, %2};" : "=l"(r) : "f"(lo), "f"(hi)); return r;
}
__device__ __forceinline__ void fma2(u64& d, u64 a, u64 b) {
    asm("fma.rn.f32x2 %0, %1, %2, %3;" : "=l"(d) : "l"(a), "l"(b), "l"(d));
}
__device__ __forceinline__ float2 unpack2(u64 v) {
    float2 f; asm("mov.b64 {%0, %1}, %2;" : "=f"(f.x), "=f"(f.y) : "l"(v)); return f;
}
__device__ __forceinline__ uint32_t smem_u32(const void* p) {
    uint32_t a;
    asm("{ .reg .u64 t; cvta.to.shared.u64 t, %1; cvt.u32.u64 %0, t; }" : "=r"(a) : "l"(p));
    return a;
}
__device__ __forceinline__ void cp_async16(uint32_t dst, const void* src) {
    asm volatile("cp.async.cg.shared.global [%0], [%1], 16;" :: "r"(dst), "l"(src) : "memory");
}
__device__ __forceinline__ void cp_commit() {
    asm volatile("cp.async.commit_group;" ::: "memory");
}
template <int N>
__device__ __forceinline__ void cp_wait() {
    asm volatile("cp.async.wait_group %0;" :: "n"(N) : "memory");
}

__device__ __forceinline__ int fetch_idx(const int* __restrict__ ei32,
                                         int is64, size_t pos) {
    int v = is64 ? ei32[2 * pos] : ei32[pos];
    v = v < 0 ? 0 : (v >= N_NODES ? N_NODES - 1 : v);
    return v;
}

// ---------------------------------------------------------------------------
// Node projection (both W_hu and W_hw via blockIdx.y) — proven kernel.
// Block (0,0) also performs index-dtype detection (edge launches after).
// ---------------------------------------------------------------------------
__global__ __launch_bounds__(256, 2)
void node_proj_kernel(const float* __restrict__ h,
                      const float* __restrict__ Whu,
                      const float* __restrict__ Whw,
                      const int* __restrict__ ei32)
{
    __shared__ __align__(16) float Wsh[32][132];
    __shared__ __align__(16) float Hsh[32][132];

    if (blockIdx.x == 0 && blockIdx.y == 0 && threadIdx.x == 0) {
        int all_zero = 1;
        for (int i = 0; i < 256; ++i)
            if (ei32[2 * i + 1] != 0) { all_zero = 0; break; }
        g_idx_is64 = all_zero;
    }

    const float* __restrict__ W   = blockIdx.y ? Whw : Whu;
    float*       __restrict__ dst = blockIdx.y ? g_HW : g_HU;

    const int tid = threadIdx.x;
    const int tx  = tid & 31;
    const int ty  = tid >> 5;
    const int n0  = blockIdx.x * 128;

    u64 acc[8][4];
#pragma unroll
    for (int p = 0; p < 8; ++p)
#pragma unroll
        for (int j = 0; j < 4; ++j) acc[p][j] = 0ULL;

#pragma unroll 1
    for (int s = 0; s < 4; ++s) {
        __syncthreads();
#pragma unroll
        for (int it = 0; it < 4; ++it) {
            int idx = it * 256 + tid;
            int o   = idx >> 3;
            int kq  = idx & 7;
            float4 w = *reinterpret_cast<const float4*>(W + (size_t)o * IN_DIM + s * 32 + kq * 4);
            Wsh[kq * 4 + 0][o] = w.x; Wsh[kq * 4 + 1][o] = w.y;
            Wsh[kq * 4 + 2][o] = w.z; Wsh[kq * 4 + 3][o] = w.w;
        }
#pragma unroll
        for (int it = 0; it < 4; ++it) {
            int idx = it * 256 + tid;
            int ln  = idx >> 3;
            int kq  = idx & 7;
            int n   = n0 + ln;
            float4 v = make_float4(0.f, 0.f, 0.f, 0.f);
            if (n < N_NODES)
                v = *reinterpret_cast<const float4*>(h + (size_t)n * IN_DIM + s * 32 + kq * 4);
            Hsh[kq * 4 + 0][ln] = v.x; Hsh[kq * 4 + 1][ln] = v.y;
            Hsh[kq * 4 + 2][ln] = v.z; Hsh[kq * 4 + 3][ln] = v.w;
        }
        __syncthreads();

#pragma unroll
        for (int k = 0; k < 32; ++k) {
            float4 w = *reinterpret_cast<const float4*>(&Wsh[k][tx * 4]);
            u64 w2[4];
            w2[0] = pack2(w.x, w.x); w2[1] = pack2(w.y, w.y);
            w2[2] = pack2(w.z, w.z); w2[3] = pack2(w.w, w.w);
            u64 ev[8];
#pragma unroll
            for (int q = 0; q < 4; ++q) {
                ulonglong2 ep = *reinterpret_cast<const ulonglong2*>(&Hsh[k][ty * 16 + q * 4]);
                ev[2 * q] = ep.x; ev[2 * q + 1] = ep.y;
            }
#pragma unroll
            for (int p = 0; p < 8; ++p)
#pragma unroll
                for (int j = 0; j < 4; ++j)
                    fma2(acc[p][j], ev[p], w2[j]);
        }
    }

#pragma unroll
    for (int p = 0; p < 8; ++p) {
        int na = n0 + ty * 16 + 2 * p;
        float2 v0 = unpack2(acc[p][0]), v1 = unpack2(acc[p][1]);
        float2 v2 = unpack2(acc[p][2]), v3 = unpack2(acc[p][3]);
        if (na < N_NODES)
            *reinterpret_cast<float4*>(dst + (size_t)na * OUT_DIM + tx * 4) =
                make_float4(v0.x, v1.x, v2.x, v3.x);
        if (na + 1 < N_NODES)
            *reinterpret_cast<float4*>(dst + (size_t)(na + 1) * OUT_DIM + tx * 4) =
                make_float4(v0.y, v1.y, v2.y, v3.y);
    }
}

// ---------------------------------------------------------------------------
// Edge kernel v5 (fixed fill): f32x2 lanes paired over K.
//   acc[edge][out] = f32x2 (even-k, odd-k partials); final = .x + .y.
//   W pre-paired in smem Wp[kp][o] (u64). E staged untransposed [edge][k]
//   via cp.async (1024 x 16B chunks = 4/thread), double-buffered.
//   Thread tile 4 edges x 4 outs; block tile 64 edges x 64 outs; occupancy 4.
//   Persistent: 20 tiles per block, grid 625 x 2.
// ---------------------------------------------------------------------------
__global__ __launch_bounds__(256, 4)
void edge_kernel(const float* __restrict__ e,
                 const int* __restrict__ ei32,
                 const float* __restrict__ We,
                 float* __restrict__ out)
{
    extern __shared__ __align__(16) char smem[];
    u64*   Wp    = reinterpret_cast<u64*>(smem + SM_WP);     // [32][64]
    float* Ebase = reinterpret_cast<float*>(smem + SM_E);    // [2][64][64]
    const uint32_t e_sm0 = smem_u32(Ebase);

    const int tid  = threadIdx.x;
    const int tx   = tid & 15;    // outs: oh + tx*4 .. +3
    const int ty   = tid >> 4;    // edges: ty*4 .. ty*4+3
    const int oh   = blockIdx.y * 64;
    const int is64 = g_idx_is64;

    // ---- one-time W pre-pairing: We[oh+o][2kq*2..] -> Wp[kp][o] ----
#pragma unroll
    for (int it = 0; it < 4; ++it) {
        int idx = it * 256 + tid;        // 0..1023
        int o   = idx & 63;
        int kq  = idx >> 6;              // 0..15 (float4 -> kpairs 2kq, 2kq+1)
        float4 w = *reinterpret_cast<const float4*>(
            We + (size_t)(oh + o) * EDGE_DIM + kq * 4);
        Wp[(2 * kq) * 64 + o]     = pack2(w.x, w.y);
        Wp[(2 * kq + 1) * 64 + o] = pack2(w.z, w.w);
    }

    const int t0 = blockIdx.x * TPB_TILES;

    // Stage fill: 64 rows x 256B = 1024 x 16B chunks; 4 chunks/thread.
    // chunk c = tid + 256*j : row = c>>4 (0..63), seg = c&15 (0..15)
    // prologue: stage tile 0 into buffer 0
#pragma unroll
    for (int j = 0; j < 4; ++j) {
        int c   = tid + 256 * j;
        int row = c >> 4;
        int sg  = c & 15;
        cp_async16(e_sm0 + row * 256 + sg * 16,
                   e + (size_t)(t0 * ETILE + row) * EDGE_DIM + sg * 4);
    }
    cp_commit();

#pragma unroll 1
    for (int t = 0; t < TPB_TILES; ++t) {
        const int buf = t & 1;
        // stage next tile into other buffer
        if (t + 1 < TPB_TILES) {
            const uint32_t dst = e_sm0 + (buf ^ 1) * 16384;
#pragma unroll
            for (int j = 0; j < 4; ++j) {
                int c   = tid + 256 * j;
                int row = c >> 4;
                int sg  = c & 15;
                cp_async16(dst + row * 256 + sg * 16,
                           e + (size_t)((t0 + t + 1) * ETILE + row) * EDGE_DIM + sg * 4);
            }
            cp_commit();
            cp_wait<1>();
        } else {
            cp_wait<0>();
        }
        __syncthreads();   // current buffer ready; also guards Wp on t==0

        // ---- mainloop: 32 k-pairs ----
        u64 acc[4][4];
#pragma unroll
        for (int p = 0; p < 4; ++p)
#pragma unroll
            for (int j = 0; j < 4; ++j) acc[p][j] = 0ULL;

        const float* E = Ebase + buf * 4096;   // [64][64]
#pragma unroll 4
        for (int kp = 0; kp < 32; ++kp) {
            u64 wv[4];
            {
                ulonglong2 wa = *reinterpret_cast<const ulonglong2*>(&Wp[kp * 64 + tx * 4]);
                ulonglong2 wb = *reinterpret_cast<const ulonglong2*>(&Wp[kp * 64 + tx * 4 + 2]);
                wv[0] = wa.x; wv[1] = wa.y; wv[2] = wb.x; wv[3] = wb.y;
            }
            u64 ev[4];
#pragma unroll
            for (int i = 0; i < 4; ++i)
                ev[i] = *reinterpret_cast<const u64*>(E + (ty * 4 + i) * 64 + kp * 2);
#pragma unroll
            for (int i = 0; i < 4; ++i)
#pragma unroll
                for (int j = 0; j < 4; ++j)
                    fma2(acc[i][j], ev[i], wv[j]);
        }

        // ---- epilogue: horizontal add + gather + store ----
        const int eb0 = (t0 + t) * ETILE;
#pragma unroll
        for (int i = 0; i < 4; ++i) {
            const int ea = eb0 + ty * 4 + i;
            const int sa = fetch_idx(ei32, is64, (size_t)ea);
            const int ta = fetch_idx(ei32, is64, (size_t)N_EDGES + ea);
            float4 A = *reinterpret_cast<const float4*>(g_HU + (size_t)sa * OUT_DIM + oh + tx * 4);
            float4 B = *reinterpret_cast<const float4*>(g_HW + (size_t)ta * OUT_DIM + oh + tx * 4);
            float2 a0 = unpack2(acc[i][0]), a1 = unpack2(acc[i][1]);
            float2 a2 = unpack2(acc[i][2]), a3 = unpack2(acc[i][3]);
            *reinterpret_cast<float4*>(out + (size_t)ea * OUT_DIM + oh + tx * 4) =
                make_float4(a0.x + a0.y + A.x + B.x,
                            a1.x + a1.y + A.y + B.y,
                            a2.x + a2.y + A.z + B.z,
                            a3.x + a3.y + A.w + B.w);
        }

        __syncthreads();   // all reads of this buffer done before refill
    }
}

extern "C" void kernel_launch(void* const* d_in, const int* in_sizes, int n_in,
                              void* d_out, int out_size)
{
    const float* h   = (const float*)d_in[0];       // [50000,128]
    const float* e   = (const float*)d_in[1];       // [800000,64]
    const int*   ei  = (const int*)d_in[2];         // [2,800000]
    const float* We  = (const float*)d_in[3];       // [128,64]
    const float* Whu = (const float*)d_in[4];       // [128,128]
    const float* Whw = (const float*)d_in[5];       // [128,128]
    float*       out = (float*)d_out;               // [800000,128]

    dim3 ngrid((N_NODES + 127) / 128, 2);
    node_proj_kernel<<<ngrid, 256>>>(h, Whu, Whw, ei);

    cudaFuncSetAttribute(edge_kernel,
                         cudaFuncAttributeMaxDynamicSharedMemorySize, SM_TOTAL);
    dim3 egrid(EGRID_X, 2);
    edge_kernel<<<egrid, 256, SM_TOTAL>>>(e, ei, We, out);
}

// round 11
// speedup vs baseline: 1.3417x; 1.3417x over previous
#include <cuda_runtime.h>
#include <cstdint>

#define N_NODES 50000
#define N_EDGES 800000
#define IN_DIM  128
#define OUT_DIM 128
#define EDGE_DIM 64
#define TPB_TILES 10            // edge tiles per block
#define EGRID_X   625           // 625 * 10 * 128 = 800000

typedef unsigned long long u64;

// Scratch for node projections (allocation-free per harness rules).
__device__ __align__(16) float g_HU[(size_t)N_NODES * OUT_DIM];
__device__ __align__(16) float g_HW[(size_t)N_NODES * OUT_DIM];
__device__ int g_idx_is64;

__device__ __forceinline__ u64 pack2(float lo, float hi) {
    u64 r; asm("mov.b64 %0, {%1, %2};" : "=l"(r) : "f"(lo), "f"(hi)); return r;
}
__device__ __forceinline__ void fma2(u64& d, u64 a, u64 b) {
    asm("fma.rn.f32x2 %0, %1, %2, %3;" : "=l"(d) : "l"(a), "l"(b), "l"(d));
}
__device__ __forceinline__ float2 unpack2(u64 v) {
    float2 f; asm("mov.b64 {%0, %1}, %2;" : "=f"(f.x), "=f"(f.y) : "l"(v)); return f;
}
__device__ __forceinline__ int clamp_idx(int v) {
    return v < 0 ? 0 : (v >= N_NODES ? N_NODES - 1 : v);
}

// ---------------------------------------------------------------------------
// Node projection (both W_hu and W_hw via blockIdx.y) — proven kernel.
// Block (0,0) also performs index-dtype detection (edge launches after).
// ---------------------------------------------------------------------------
__global__ __launch_bounds__(256, 2)
void node_proj_kernel(const float* __restrict__ h,
                      const float* __restrict__ Whu,
                      const float* __restrict__ Whw,
                      const int* __restrict__ ei32)
{
    __shared__ __align__(16) float Wsh[32][132];
    __shared__ __align__(16) float Hsh[32][132];

    if (blockIdx.x == 0 && blockIdx.y == 0 && threadIdx.x == 0) {
        int all_zero = 1;
        for (int i = 0; i < 256; ++i)
            if (ei32[2 * i + 1] != 0) { all_zero = 0; break; }
        g_idx_is64 = all_zero;
    }

    const float* __restrict__ W   = blockIdx.y ? Whw : Whu;
    float*       __restrict__ dst = blockIdx.y ? g_HW : g_HU;

    const int tid = threadIdx.x;
    const int tx  = tid & 31;
    const int ty  = tid >> 5;
    const int n0  = blockIdx.x * 128;

    u64 acc[8][4];
#pragma unroll
    for (int p = 0; p < 8; ++p)
#pragma unroll
        for (int j = 0; j < 4; ++j) acc[p][j] = 0ULL;

#pragma unroll 1
    for (int s = 0; s < 4; ++s) {
        __syncthreads();
#pragma unroll
        for (int it = 0; it < 4; ++it) {
            int idx = it * 256 + tid;
            int o   = idx >> 3;
            int kq  = idx & 7;
            float4 w = *reinterpret_cast<const float4*>(W + (size_t)o * IN_DIM + s * 32 + kq * 4);
            Wsh[kq * 4 + 0][o] = w.x; Wsh[kq * 4 + 1][o] = w.y;
            Wsh[kq * 4 + 2][o] = w.z; Wsh[kq * 4 + 3][o] = w.w;
        }
#pragma unroll
        for (int it = 0; it < 4; ++it) {
            int idx = it * 256 + tid;
            int ln  = idx >> 3;
            int kq  = idx & 7;
            int n   = n0 + ln;
            float4 v = make_float4(0.f, 0.f, 0.f, 0.f);
            if (n < N_NODES)
                v = *reinterpret_cast<const float4*>(h + (size_t)n * IN_DIM + s * 32 + kq * 4);
            Hsh[kq * 4 + 0][ln] = v.x; Hsh[kq * 4 + 1][ln] = v.y;
            Hsh[kq * 4 + 2][ln] = v.z; Hsh[kq * 4 + 3][ln] = v.w;
        }
        __syncthreads();

#pragma unroll
        for (int k = 0; k < 32; ++k) {
            float4 w = *reinterpret_cast<const float4*>(&Wsh[k][tx * 4]);
            u64 w2[4];
            w2[0] = pack2(w.x, w.x); w2[1] = pack2(w.y, w.y);
            w2[2] = pack2(w.z, w.z); w2[3] = pack2(w.w, w.w);
            u64 ev[8];
#pragma unroll
            for (int q = 0; q < 4; ++q) {
                ulonglong2 ep = *reinterpret_cast<const ulonglong2*>(&Hsh[k][ty * 16 + q * 4]);
                ev[2 * q] = ep.x; ev[2 * q + 1] = ep.y;
            }
#pragma unroll
            for (int p = 0; p < 8; ++p)
#pragma unroll
                for (int j = 0; j < 4; ++j)
                    fma2(acc[p][j], ev[p], w2[j]);
        }
    }

#pragma unroll
    for (int p = 0; p < 8; ++p) {
        int na = n0 + ty * 16 + 2 * p;
        float2 v0 = unpack2(acc[p][0]), v1 = unpack2(acc[p][1]);
        float2 v2 = unpack2(acc[p][2]), v3 = unpack2(acc[p][3]);
        if (na < N_NODES)
            *reinterpret_cast<float4*>(dst + (size_t)na * OUT_DIM + tx * 4) =
                make_float4(v0.x, v1.x, v2.x, v3.x);
        if (na + 1 < N_NODES)
            *reinterpret_cast<float4*>(dst + (size_t)(na + 1) * OUT_DIM + tx * 4) =
                make_float4(v0.y, v1.y, v2.y, v3.y);
    }
}

// ---------------------------------------------------------------------------
// Fused edge kernel v6: R8 multi-tile persistent structure with
//   - Esh row stride 136 floats -> staging STS conflict-free, 16B aligned
//   - __ldcg on streamed / L2-resident loads (e, indices, hu/hw gathers)
//   - vectorized hoisted index loads (int4) in the epilogue
// Grid 625 x 2; block tile 128 edges x 64 outs; 10 tiles/block; occupancy 3.
// ---------------------------------------------------------------------------
__global__ __launch_bounds__(256, 3)
void edge_kernel(const float* __restrict__ e,
                 const int* __restrict__ ei32,
                 const float* __restrict__ We,
                 float* __restrict__ out)
{
    __shared__ __align__(16) float Wsh[EDGE_DIM][68];   // [k][o-half]  17.4KB
    __shared__ __align__(16) float Esh[2][16][136];     // double buf   17.4KB

    const int tid  = threadIdx.x;
    const int tx   = tid & 15;   // outs: oh + tx*4 .. +3
    const int ty   = tid >> 4;   // edges: ty*8 .. ty*8+7
    const int oh   = blockIdx.y * 64;
    const int is64 = g_idx_is64;

    // One-time W fill (conflict-free mapping; LDG mostly L2-hits).
#pragma unroll
    for (int it = 0; it < 4; ++it) {
        int idx = it * 256 + tid;       // 0..1023
        int o   = idx & 63;
        int kq  = idx >> 6;             // 0..15
        float4 w = *reinterpret_cast<const float4*>(
            We + (size_t)(oh + o) * EDGE_DIM + kq * 4);
        Wsh[kq * 4 + 0][o] = w.x;
        Wsh[kq * 4 + 1][o] = w.y;
        Wsh[kq * 4 + 2][o] = w.z;
        Wsh[kq * 4 + 3][o] = w.w;
    }

    // E stage fill assignment: thread covers float4 idx {tid, 256+tid} of 512
    const int le0 = tid >> 2,         kq0 = tid & 3;
    const int le1 = (256 + tid) >> 2, kq1 = (256 + tid) & 3;

    const int t0 = blockIdx.x * TPB_TILES;
    const int NS = 4 * TPB_TILES;            // stages total

    // Prefetch + fill stage 0 of tile 0 into buffer 0.
    float4 pf0 = __ldcg(reinterpret_cast<const float4*>(
        e + (size_t)(t0 * 128 + le0) * EDGE_DIM + kq0 * 4));
    float4 pf1 = __ldcg(reinterpret_cast<const float4*>(
        e + (size_t)(t0 * 128 + le1) * EDGE_DIM + kq1 * 4));
    Esh[0][kq0 * 4 + 0][le0] = pf0.x; Esh[0][kq0 * 4 + 1][le0] = pf0.y;
    Esh[0][kq0 * 4 + 2][le0] = pf0.z; Esh[0][kq0 * 4 + 3][le0] = pf0.w;
    Esh[0][kq1 * 4 + 0][le1] = pf1.x; Esh[0][kq1 * 4 + 1][le1] = pf1.y;
    Esh[0][kq1 * 4 + 2][le1] = pf1.z; Esh[0][kq1 * 4 + 3][le1] = pf1.w;
    __syncthreads();

    u64 acc[4][4];

#pragma unroll 1
    for (int gs = 0; gs < NS; ++gs) {
        const int cur  = gs & 1;
        const int tile = gs >> 2;
        const int s    = gs & 3;

        // prefetch next stage (possibly next tile's stage 0)
        if (gs + 1 < NS) {
            const int nt = (gs + 1) >> 2, nss = (gs + 1) & 3;
            pf0 = __ldcg(reinterpret_cast<const float4*>(
                e + (size_t)((t0 + nt) * 128 + le0) * EDGE_DIM + nss * 16 + kq0 * 4));
            pf1 = __ldcg(reinterpret_cast<const float4*>(
                e + (size_t)((t0 + nt) * 128 + le1) * EDGE_DIM + nss * 16 + kq1 * 4));
        }

        if (s == 0) {
#pragma unroll
            for (int p = 0; p < 4; ++p)
#pragma unroll
                for (int j = 0; j < 4; ++j) acc[p][j] = 0ULL;
        }

        // ---- 16 k-steps on Esh[cur] (R6/R8-proven inner loop) ----
#pragma unroll
        for (int k = 0; k < 16; ++k) {
            int kk = s * 16 + k;
            float4 w = *reinterpret_cast<const float4*>(&Wsh[kk][tx * 4]);
            u64 w2[4];
            w2[0] = pack2(w.x, w.x); w2[1] = pack2(w.y, w.y);
            w2[2] = pack2(w.z, w.z); w2[3] = pack2(w.w, w.w);
            u64 ev[4];
            {
                ulonglong2 ea = *reinterpret_cast<const ulonglong2*>(&Esh[cur][k][ty * 8]);
                ulonglong2 eb = *reinterpret_cast<const ulonglong2*>(&Esh[cur][k][ty * 8 + 4]);
                ev[0] = ea.x; ev[1] = ea.y; ev[2] = eb.x; ev[3] = eb.y;
            }
#pragma unroll
            for (int p = 0; p < 4; ++p)
#pragma unroll
                for (int j = 0; j < 4; ++j)
                    fma2(acc[p][j], ev[p], w2[j]);
        }

        // ---- tile finished: gather + store epilogue (no smem touched) ----
        if (s == 3) {
            const int base = (t0 + tile) * 128 + ty * 8;   // 8 consecutive edges
            int sidx[8], tidx[8];
            if (!is64) {
                int4 a = __ldcg(reinterpret_cast<const int4*>(ei32 + base));
                int4 b = __ldcg(reinterpret_cast<const int4*>(ei32 + base + 4));
                int4 c = __ldcg(reinterpret_cast<const int4*>(ei32 + N_EDGES + base));
                int4 d = __ldcg(reinterpret_cast<const int4*>(ei32 + N_EDGES + base + 4));
                sidx[0] = a.x; sidx[1] = a.y; sidx[2] = a.z; sidx[3] = a.w;
                sidx[4] = b.x; sidx[5] = b.y; sidx[6] = b.z; sidx[7] = b.w;
                tidx[0] = c.x; tidx[1] = c.y; tidx[2] = c.z; tidx[3] = c.w;
                tidx[4] = d.x; tidx[5] = d.y; tidx[6] = d.z; tidx[7] = d.w;
            } else {
#pragma unroll
                for (int i = 0; i < 8; ++i) {
                    sidx[i] = ei32[2 * (size_t)(base + i)];
                    tidx[i] = ei32[2 * ((size_t)N_EDGES + base + i)];
                }
            }
#pragma unroll
            for (int i = 0; i < 8; ++i) {
                sidx[i] = clamp_idx(sidx[i]);
                tidx[i] = clamp_idx(tidx[i]);
            }

#pragma unroll
            for (int p = 0; p < 4; ++p) {
                int ea = base + 2 * p;
                float4 A = __ldcg(reinterpret_cast<const float4*>(
                    g_HU + (size_t)sidx[2 * p] * OUT_DIM + oh + tx * 4));
                float4 B = __ldcg(reinterpret_cast<const float4*>(
                    g_HW + (size_t)tidx[2 * p] * OUT_DIM + oh + tx * 4));
                float4 C = __ldcg(reinterpret_cast<const float4*>(
                    g_HU + (size_t)sidx[2 * p + 1] * OUT_DIM + oh + tx * 4));
                float4 D = __ldcg(reinterpret_cast<const float4*>(
                    g_HW + (size_t)tidx[2 * p + 1] * OUT_DIM + oh + tx * 4));

                float2 v0 = unpack2(acc[p][0]), v1 = unpack2(acc[p][1]);
                float2 v2 = unpack2(acc[p][2]), v3 = unpack2(acc[p][3]);

                *reinterpret_cast<float4*>(out + (size_t)ea * OUT_DIM + oh + tx * 4) =
                    make_float4(v0.x + A.x + B.x, v1.x + A.y + B.y,
                                v2.x + A.z + B.z, v3.x + A.w + B.w);
                *reinterpret_cast<float4*>(out + (size_t)(ea + 1) * OUT_DIM + oh + tx * 4) =
                    make_float4(v0.y + C.x + D.x, v1.y + C.y + D.y,
                                v2.y + C.z + D.z, v3.y + C.w + D.w);
            }
        }

        // ---- publish prefetched stage into the other buffer (conflict-free) ----
        if (gs + 1 < NS) {
            const int nxt = cur ^ 1;
            Esh[nxt][kq0 * 4 + 0][le0] = pf0.x; Esh[nxt][kq0 * 4 + 1][le0] = pf0.y;
            Esh[nxt][kq0 * 4 + 2][le0] = pf0.z; Esh[nxt][kq0 * 4 + 3][le0] = pf0.w;
            Esh[nxt][kq1 * 4 + 0][le1] = pf1.x; Esh[nxt][kq1 * 4 + 1][le1] = pf1.y;
            Esh[nxt][kq1 * 4 + 2][le1] = pf1.z; Esh[nxt][kq1 * 4 + 3][le1] = pf1.w;
            __syncthreads();
        }
    }
}

extern "C" void kernel_launch(void* const* d_in, const int* in_sizes, int n_in,
                              void* d_out, int out_size)
{
    const float* h   = (const float*)d_in[0];       // [50000,128]
    const float* e   = (const float*)d_in[1];       // [800000,64]
    const int*   ei  = (const int*)d_in[2];         // [2,800000]
    const float* We  = (const float*)d_in[3];       // [128,64]
    const float* Whu = (const float*)d_in[4];       // [128,128]
    const float* Whw = (const float*)d_in[5];       // [128,128]
    float*       out = (float*)d_out;               // [800000,128]

    dim3 ngrid((N_NODES + 127) / 128, 2);
    node_proj_kernel<<<ngrid, 256>>>(h, Whu, Whw, ei);

    dim3 egrid(EGRID_X, 2);
    edge_kernel<<<egrid, 256>>>(e, ei, We, out);
}

// round 12
// speedup vs baseline: 1.3508x; 1.0068x over previous
#include <cuda_runtime.h>
#include <cstdint>

#define N_NODES 50000
#define N_EDGES 800000
#define IN_DIM  128
#define OUT_DIM 128
#define EDGE_DIM 64
#define TPB_TILES 10            // edge tiles per block
#define EGRID_X   625           // 625 * 10 * 128 = 800000

// dynamic smem layout (bytes)
#define SM_W      0             // Wsh[64][128] f32 = 32768
#define SM_E      32768         // Esh[2][16][132] f32 = 16896
#define SM_TOTAL  49664

typedef unsigned long long u64;

// Scratch for node projections (allocation-free per harness rules).
__device__ __align__(16) float g_HU[(size_t)N_NODES * OUT_DIM];
__device__ __align__(16) float g_HW[(size_t)N_NODES * OUT_DIM];
__device__ int g_idx_is64;

__device__ __forceinline__ u64 pack2(float lo, float hi) {
    u64 r; asm("mov.b64 %0, {%1, %2};" : "=l"(r) : "f"(lo), "f"(hi)); return r;
}
__device__ __forceinline__ void fma2(u64& d, u64 a, u64 b) {
    asm("fma.rn.f32x2 %0, %1, %2, %3;" : "=l"(d) : "l"(a), "l"(b), "l"(d));
}
__device__ __forceinline__ float2 unpack2(u64 v) {
    float2 f; asm("mov.b64 {%0, %1}, %2;" : "=f"(f.x), "=f"(f.y) : "l"(v)); return f;
}
__device__ __forceinline__ int fetch_idx(const int* __restrict__ ei32,
                                         int is64, size_t pos) {
    int v = is64 ? ei32[2 * pos] : ei32[pos];
    v = v < 0 ? 0 : (v >= N_NODES ? N_NODES - 1 : v);
    return v;
}

// ---------------------------------------------------------------------------
// Node projection (both W_hu and W_hw via blockIdx.y) — proven kernel.
// Block (0,0) also performs index-dtype detection (edge launches after).
// ---------------------------------------------------------------------------
__global__ __launch_bounds__(256, 2)
void node_proj_kernel(const float* __restrict__ h,
                      const float* __restrict__ Whu,
                      const float* __restrict__ Whw,
                      const int* __restrict__ ei32)
{
    __shared__ __align__(16) float Wsh[32][132];
    __shared__ __align__(16) float Hsh[32][132];

    if (blockIdx.x == 0 && blockIdx.y == 0 && threadIdx.x == 0) {
        int all_zero = 1;
        for (int i = 0; i < 256; ++i)
            if (ei32[2 * i + 1] != 0) { all_zero = 0; break; }
        g_idx_is64 = all_zero;
    }

    const float* __restrict__ W   = blockIdx.y ? Whw : Whu;
    float*       __restrict__ dst = blockIdx.y ? g_HW : g_HU;

    const int tid = threadIdx.x;
    const int tx  = tid & 31;
    const int ty  = tid >> 5;
    const int n0  = blockIdx.x * 128;

    u64 acc[8][4];
#pragma unroll
    for (int p = 0; p < 8; ++p)
#pragma unroll
        for (int j = 0; j < 4; ++j) acc[p][j] = 0ULL;

#pragma unroll 1
    for (int s = 0; s < 4; ++s) {
        __syncthreads();
#pragma unroll
        for (int it = 0; it < 4; ++it) {
            int idx = it * 256 + tid;
            int o   = idx >> 3;
            int kq  = idx & 7;
            float4 w = *reinterpret_cast<const float4*>(W + (size_t)o * IN_DIM + s * 32 + kq * 4);
            Wsh[kq * 4 + 0][o] = w.x; Wsh[kq * 4 + 1][o] = w.y;
            Wsh[kq * 4 + 2][o] = w.z; Wsh[kq * 4 + 3][o] = w.w;
        }
#pragma unroll
        for (int it = 0; it < 4; ++it) {
            int idx = it * 256 + tid;
            int ln  = idx >> 3;
            int kq  = idx & 7;
            int n   = n0 + ln;
            float4 v = make_float4(0.f, 0.f, 0.f, 0.f);
            if (n < N_NODES)
                v = *reinterpret_cast<const float4*>(h + (size_t)n * IN_DIM + s * 32 + kq * 4);
            Hsh[kq * 4 + 0][ln] = v.x; Hsh[kq * 4 + 1][ln] = v.y;
            Hsh[kq * 4 + 2][ln] = v.z; Hsh[kq * 4 + 3][ln] = v.w;
        }
        __syncthreads();

#pragma unroll
        for (int k = 0; k < 32; ++k) {
            float4 w = *reinterpret_cast<const float4*>(&Wsh[k][tx * 4]);
            u64 w2[4];
            w2[0] = pack2(w.x, w.x); w2[1] = pack2(w.y, w.y);
            w2[2] = pack2(w.z, w.z); w2[3] = pack2(w.w, w.w);
            u64 ev[8];
#pragma unroll
            for (int q = 0; q < 4; ++q) {
                ulonglong2 ep = *reinterpret_cast<const ulonglong2*>(&Hsh[k][ty * 16 + q * 4]);
                ev[2 * q] = ep.x; ev[2 * q + 1] = ep.y;
            }
#pragma unroll
            for (int p = 0; p < 8; ++p)
#pragma unroll
                for (int j = 0; j < 4; ++j)
                    fma2(acc[p][j], ev[p], w2[j]);
        }
    }

#pragma unroll
    for (int p = 0; p < 8; ++p) {
        int na = n0 + ty * 16 + 2 * p;
        float2 v0 = unpack2(acc[p][0]), v1 = unpack2(acc[p][1]);
        float2 v2 = unpack2(acc[p][2]), v3 = unpack2(acc[p][3]);
        if (na < N_NODES)
            *reinterpret_cast<float4*>(dst + (size_t)na * OUT_DIM + tx * 4) =
                make_float4(v0.x, v1.x, v2.x, v3.x);
        if (na + 1 < N_NODES)
            *reinterpret_cast<float4*>(dst + (size_t)(na + 1) * OUT_DIM + tx * 4) =
                make_float4(v0.y, v1.y, v2.y, v3.y);
    }
}

// ---------------------------------------------------------------------------
// Fused edge kernel v7: R8 persistent structure, thread tile 8 edges x 8 outs.
// Thread outs = {tx*4..+3} U {64+tx*4..+3}: both W reads contiguous 256B
// (no strided conflicts). Block tile 128 edges x 128 outs, grid 625, occ 2.
// Staging and epilogue byte-identical in style to R8 (plain loads, scalar idx).
// ---------------------------------------------------------------------------
__global__ __launch_bounds__(256, 2)
void edge_kernel(const float* __restrict__ e,
                 const int* __restrict__ ei32,
                 const float* __restrict__ We,
                 float* __restrict__ out)
{
    extern __shared__ __align__(16) char smem[];
    float* Wsh = reinterpret_cast<float*>(smem + SM_W);   // [64][128]
    float* Esh = reinterpret_cast<float*>(smem + SM_E);   // [2][16][132]

    const int tid  = threadIdx.x;
    const int tx   = tid & 15;   // out groups: tx*4 and 64+tx*4
    const int ty   = tid >> 4;   // edges: ty*8 .. ty*8+7
    const int is64 = g_idx_is64;

    // One-time W fill: We[o][kq*4..] -> Wsh[kq*4+j][o], 2048 float4s.
#pragma unroll
    for (int it = 0; it < 8; ++it) {
        int idx = it * 256 + tid;       // 0..2047
        int o   = idx >> 4;             // 0..127
        int kq  = idx & 15;             // 0..15
        float4 w = reinterpret_cast<const float4*>(We)[idx];
        Wsh[(kq * 4 + 0) * 128 + o] = w.x;
        Wsh[(kq * 4 + 1) * 128 + o] = w.y;
        Wsh[(kq * 4 + 2) * 128 + o] = w.z;
        Wsh[(kq * 4 + 3) * 128 + o] = w.w;
    }

    // E stage fill assignment: thread covers float4 idx {tid, 256+tid} of 512
    const int le0 = tid >> 2,         kq0 = tid & 3;
    const int le1 = (256 + tid) >> 2, kq1 = (256 + tid) & 3;

    const int t0 = blockIdx.x * TPB_TILES;
    const int NS = 4 * TPB_TILES;

    // Prefetch + fill stage 0 of tile 0 into buffer 0.
    float4 pf0 = *reinterpret_cast<const float4*>(
        e + (size_t)(t0 * 128 + le0) * EDGE_DIM + kq0 * 4);
    float4 pf1 = *reinterpret_cast<const float4*>(
        e + (size_t)(t0 * 128 + le1) * EDGE_DIM + kq1 * 4);
    Esh[(kq0 * 4 + 0) * 132 + le0] = pf0.x; Esh[(kq0 * 4 + 1) * 132 + le0] = pf0.y;
    Esh[(kq0 * 4 + 2) * 132 + le0] = pf0.z; Esh[(kq0 * 4 + 3) * 132 + le0] = pf0.w;
    Esh[(kq1 * 4 + 0) * 132 + le1] = pf1.x; Esh[(kq1 * 4 + 1) * 132 + le1] = pf1.y;
    Esh[(kq1 * 4 + 2) * 132 + le1] = pf1.z; Esh[(kq1 * 4 + 3) * 132 + le1] = pf1.w;
    __syncthreads();

    u64 acc[4][8];

#pragma unroll 1
    for (int gs = 0; gs < NS; ++gs) {
        const int cur  = gs & 1;
        const int tile = gs >> 2;
        const int s    = gs & 3;
        float* Ecur = Esh + cur * (16 * 132);

        // prefetch next stage (possibly next tile's stage 0)
        if (gs + 1 < NS) {
            const int nt = (gs + 1) >> 2, nss = (gs + 1) & 3;
            pf0 = *reinterpret_cast<const float4*>(
                e + (size_t)((t0 + nt) * 128 + le0) * EDGE_DIM + nss * 16 + kq0 * 4);
            pf1 = *reinterpret_cast<const float4*>(
                e + (size_t)((t0 + nt) * 128 + le1) * EDGE_DIM + nss * 16 + kq1 * 4);
        }

        if (s == 0) {
#pragma unroll
            for (int p = 0; p < 4; ++p)
#pragma unroll
                for (int j = 0; j < 8; ++j) acc[p][j] = 0ULL;
        }

        // ---- 16 k-steps: 32 fma2 per k, W reads contiguous (no conflicts) ----
#pragma unroll
        for (int k = 0; k < 16; ++k) {
            int kk = s * 16 + k;
            float4 wa = *reinterpret_cast<const float4*>(&Wsh[kk * 128 + tx * 4]);
            float4 wb = *reinterpret_cast<const float4*>(&Wsh[kk * 128 + 64 + tx * 4]);
            u64 w2[8];
            w2[0] = pack2(wa.x, wa.x); w2[1] = pack2(wa.y, wa.y);
            w2[2] = pack2(wa.z, wa.z); w2[3] = pack2(wa.w, wa.w);
            w2[4] = pack2(wb.x, wb.x); w2[5] = pack2(wb.y, wb.y);
            w2[6] = pack2(wb.z, wb.z); w2[7] = pack2(wb.w, wb.w);
            u64 ev[4];
            {
                ulonglong2 ea = *reinterpret_cast<const ulonglong2*>(&Ecur[k * 132 + ty * 8]);
                ulonglong2 eb = *reinterpret_cast<const ulonglong2*>(&Ecur[k * 132 + ty * 8 + 4]);
                ev[0] = ea.x; ev[1] = ea.y; ev[2] = eb.x; ev[3] = eb.y;
            }
#pragma unroll
            for (int p = 0; p < 4; ++p)
#pragma unroll
                for (int j = 0; j < 8; ++j)
                    fma2(acc[p][j], ev[p], w2[j]);
        }

        // ---- tile finished: gather + store epilogue (both column groups) ----
        if (s == 3) {
            const int eb0 = (t0 + tile) * 128;
#pragma unroll
            for (int p = 0; p < 4; ++p) {
                int ea = eb0 + ty * 8 + 2 * p;
                int sa = fetch_idx(ei32, is64, (size_t)ea);
                int ta = fetch_idx(ei32, is64, (size_t)N_EDGES + ea);
                int sb = fetch_idx(ei32, is64, (size_t)ea + 1);
                int tb = fetch_idx(ei32, is64, (size_t)N_EDGES + ea + 1);

                float2 v0 = unpack2(acc[p][0]), v1 = unpack2(acc[p][1]);
                float2 v2 = unpack2(acc[p][2]), v3 = unpack2(acc[p][3]);
                float2 v4 = unpack2(acc[p][4]), v5 = unpack2(acc[p][5]);
                float2 v6 = unpack2(acc[p][6]), v7 = unpack2(acc[p][7]);

                const float* huA = g_HU + (size_t)sa * OUT_DIM;
                const float* hwA = g_HW + (size_t)ta * OUT_DIM;
                const float* huB = g_HU + (size_t)sb * OUT_DIM;
                const float* hwB = g_HW + (size_t)tb * OUT_DIM;
                float* oA = out + (size_t)ea * OUT_DIM;
                float* oB = out + (size_t)(ea + 1) * OUT_DIM;

                float4 A0 = *reinterpret_cast<const float4*>(huA + tx * 4);
                float4 B0 = *reinterpret_cast<const float4*>(hwA + tx * 4);
                float4 A1 = *reinterpret_cast<const float4*>(huA + 64 + tx * 4);
                float4 B1 = *reinterpret_cast<const float4*>(hwA + 64 + tx * 4);
                *reinterpret_cast<float4*>(oA + tx * 4) =
                    make_float4(v0.x + A0.x + B0.x, v1.x + A0.y + B0.y,
                                v2.x + A0.z + B0.z, v3.x + A0.w + B0.w);
                *reinterpret_cast<float4*>(oA + 64 + tx * 4) =
                    make_float4(v4.x + A1.x + B1.x, v5.x + A1.y + B1.y,
                                v6.x + A1.z + B1.z, v7.x + A1.w + B1.w);

                float4 C0 = *reinterpret_cast<const float4*>(huB + tx * 4);
                float4 D0 = *reinterpret_cast<const float4*>(hwB + tx * 4);
                float4 C1 = *reinterpret_cast<const float4*>(huB + 64 + tx * 4);
                float4 D1 = *reinterpret_cast<const float4*>(hwB + 64 + tx * 4);
                *reinterpret_cast<float4*>(oB + tx * 4) =
                    make_float4(v0.y + C0.x + D0.x, v1.y + C0.y + D0.y,
                                v2.y + C0.z + D0.z, v3.y + C0.w + D0.w);
                *reinterpret_cast<float4*>(oB + 64 + tx * 4) =
                    make_float4(v4.y + C1.x + D1.x, v5.y + C1.y + D1.y,
                                v6.y + C1.z + D1.z, v7.y + C1.w + D1.w);
            }
        }

        // ---- publish prefetched stage into the other buffer ----
        if (gs + 1 < NS) {
            float* En = Esh + (cur ^ 1) * (16 * 132);
            En[(kq0 * 4 + 0) * 132 + le0] = pf0.x; En[(kq0 * 4 + 1) * 132 + le0] = pf0.y;
            En[(kq0 * 4 + 2) * 132 + le0] = pf0.z; En[(kq0 * 4 + 3) * 132 + le0] = pf0.w;
            En[(kq1 * 4 + 0) * 132 + le1] = pf1.x; En[(kq1 * 4 + 1) * 132 + le1] = pf1.y;
            En[(kq1 * 4 + 2) * 132 + le1] = pf1.z; En[(kq1 * 4 + 3) * 132 + le1] = pf1.w;
            __syncthreads();
        }
    }
}

extern "C" void kernel_launch(void* const* d_in, const int* in_sizes, int n_in,
                              void* d_out, int out_size)
{
    const float* h   = (const float*)d_in[0];       // [50000,128]
    const float* e   = (const float*)d_in[1];       // [800000,64]
    const int*   ei  = (const int*)d_in[2];         // [2,800000]
    const float* We  = (const float*)d_in[3];       // [128,64]
    const float* Whu = (const float*)d_in[4];       // [128,128]
    const float* Whw = (const float*)d_in[5];       // [128,128]
    float*       out = (float*)d_out;               // [800000,128]

    dim3 ngrid((N_NODES + 127) / 128, 2);
    node_proj_kernel<<<ngrid, 256>>>(h, Whu, Whw, ei);

    cudaFuncSetAttribute(edge_kernel,
                         cudaFuncAttributeMaxDynamicSharedMemorySize, SM_TOTAL);
    edge_kernel<<<EGRID_X, 256, SM_TOTAL>>>(e, ei, We, out);
}

// round 13
// speedup vs baseline: 1.4538x; 1.0763x over previous
#include <cuda_runtime.h>
#include <cstdint>

#define N_NODES 50000
#define N_EDGES 800000
#define IN_DIM  128
#define OUT_DIM 128
#define EDGE_DIM 64

#define ETILE      64                    // edges per tile
#define NTILES_TOT 12500                 // 800000 / 64
#define EGRID      592                   // 148 SMs * occ 4 -> single wave

typedef unsigned long long u64;

// Scratch for node projections (allocation-free per harness rules).
__device__ __align__(16) float g_HU[(size_t)N_NODES * OUT_DIM];
__device__ __align__(16) float g_HW[(size_t)N_NODES * OUT_DIM];
__device__ int g_idx_is64;

__device__ __forceinline__ u64 pack2(float lo, float hi) {
    u64 r; asm("mov.b64 %0, {%1, %2};" : "=l"(r) : "f"(lo), "f"(hi)); return r;
}
__device__ __forceinline__ void fma2(u64& d, u64 a, u64 b) {
    asm("fma.rn.f32x2 %0, %1, %2, %3;" : "=l"(d) : "l"(a), "l"(b), "l"(d));
}
__device__ __forceinline__ float2 unpack2(u64 v) {
    float2 f; asm("mov.b64 {%0, %1}, %2;" : "=f"(f.x), "=f"(f.y) : "l"(v)); return f;
}
__device__ __forceinline__ int fetch_idx(const int* __restrict__ ei32,
                                         int is64, size_t pos) {
    int v = is64 ? ei32[2 * pos] : ei32[pos];
    v = v < 0 ? 0 : (v >= N_NODES ? N_NODES - 1 : v);
    return v;
}

// ---------------------------------------------------------------------------
// Node projection (both W_hu and W_hw via blockIdx.y) — proven kernel.
// Block (0,0) also performs index-dtype detection (edge launches after).
// ---------------------------------------------------------------------------
__global__ __launch_bounds__(256, 2)
void node_proj_kernel(const float* __restrict__ h,
                      const float* __restrict__ Whu,
                      const float* __restrict__ Whw,
                      const int* __restrict__ ei32)
{
    __shared__ __align__(16) float Wsh[32][132];
    __shared__ __align__(16) float Hsh[32][132];

    if (blockIdx.x == 0 && blockIdx.y == 0 && threadIdx.x == 0) {
        int all_zero = 1;
        for (int i = 0; i < 256; ++i)
            if (ei32[2 * i + 1] != 0) { all_zero = 0; break; }
        g_idx_is64 = all_zero;
    }

    const float* __restrict__ W   = blockIdx.y ? Whw : Whu;
    float*       __restrict__ dst = blockIdx.y ? g_HW : g_HU;

    const int tid = threadIdx.x;
    const int tx  = tid & 31;
    const int ty  = tid >> 5;
    const int n0  = blockIdx.x * 128;

    u64 acc[8][4];
#pragma unroll
    for (int p = 0; p < 8; ++p)
#pragma unroll
        for (int j = 0; j < 4; ++j) acc[p][j] = 0ULL;

#pragma unroll 1
    for (int s = 0; s < 4; ++s) {
        __syncthreads();
#pragma unroll
        for (int it = 0; it < 4; ++it) {
            int idx = it * 256 + tid;
            int o   = idx >> 3;
            int kq  = idx & 7;
            float4 w = *reinterpret_cast<const float4*>(W + (size_t)o * IN_DIM + s * 32 + kq * 4);
            Wsh[kq * 4 + 0][o] = w.x; Wsh[kq * 4 + 1][o] = w.y;
            Wsh[kq * 4 + 2][o] = w.z; Wsh[kq * 4 + 3][o] = w.w;
        }
#pragma unroll
        for (int it = 0; it < 4; ++it) {
            int idx = it * 256 + tid;
            int ln  = idx >> 3;
            int kq  = idx & 7;
            int n   = n0 + ln;
            float4 v = make_float4(0.f, 0.f, 0.f, 0.f);
            if (n < N_NODES)
                v = *reinterpret_cast<const float4*>(h + (size_t)n * IN_DIM + s * 32 + kq * 4);
            Hsh[kq * 4 + 0][ln] = v.x; Hsh[kq * 4 + 1][ln] = v.y;
            Hsh[kq * 4 + 2][ln] = v.z; Hsh[kq * 4 + 3][ln] = v.w;
        }
        __syncthreads();

#pragma unroll
        for (int k = 0; k < 32; ++k) {
            float4 w = *reinterpret_cast<const float4*>(&Wsh[k][tx * 4]);
            u64 w2[4];
            w2[0] = pack2(w.x, w.x); w2[1] = pack2(w.y, w.y);
            w2[2] = pack2(w.z, w.z); w2[3] = pack2(w.w, w.w);
            u64 ev[8];
#pragma unroll
            for (int q = 0; q < 4; ++q) {
                ulonglong2 ep = *reinterpret_cast<const ulonglong2*>(&Hsh[k][ty * 16 + q * 4]);
                ev[2 * q] = ep.x; ev[2 * q + 1] = ep.y;
            }
#pragma unroll
            for (int p = 0; p < 8; ++p)
#pragma unroll
                for (int j = 0; j < 4; ++j)
                    fma2(acc[p][j], ev[p], w2[j]);
        }
    }

#pragma unroll
    for (int p = 0; p < 8; ++p) {
        int na = n0 + ty * 16 + 2 * p;
        float2 v0 = unpack2(acc[p][0]), v1 = unpack2(acc[p][1]);
        float2 v2 = unpack2(acc[p][2]), v3 = unpack2(acc[p][3]);
        if (na < N_NODES)
            *reinterpret_cast<float4*>(dst + (size_t)na * OUT_DIM + tx * 4) =
                make_float4(v0.x, v1.x, v2.x, v3.x);
        if (na + 1 < N_NODES)
            *reinterpret_cast<float4*>(dst + (size_t)(na + 1) * OUT_DIM + tx * 4) =
                make_float4(v0.y, v1.y, v2.y, v3.y);
    }
}

// ---------------------------------------------------------------------------
// Fused edge kernel v8: f32x2 paired over OUTPUT pairs.
//   acc[edge i][pair j] = sum_k e * (W[o2j], W[o2j+1])  -- W pairs come free
//   from contiguous float4 LDS (reinterpreted); only e is duplicated (4 movs).
//   Thread tile 4 edges x 8 outs (16 u64 accs); block 64 edges x 128 outs.
//   Occupancy 4, grid 592 (single wave), strided persistent tiles.
//   Staging: Esh[2][16][68] transposed, double-buffered, 1 barrier/stage.
// ---------------------------------------------------------------------------
__global__ __launch_bounds__(256, 4)
void edge_kernel(const float* __restrict__ e,
                 const int* __restrict__ ei32,
                 const float* __restrict__ We,
                 float* __restrict__ out)
{
    __shared__ __align__(16) float Wsh[EDGE_DIM][128];   // [k][o]      32 KB
    __shared__ __align__(16) float Esh[2][16][68];       // [buf][k][e]  8.7 KB

    const int tid  = threadIdx.x;
    const int tx   = tid & 15;   // out quads: tx*4 and 64+tx*4
    const int ty   = tid >> 4;   // edges: ty*4 .. ty*4+3
    const int bid  = blockIdx.x;
    const int is64 = g_idx_is64;

    // One-time W fill: We[o][kq*4..] -> Wsh[kq*4+j][o], 2048 float4s.
#pragma unroll
    for (int it = 0; it < 8; ++it) {
        int idx = it * 256 + tid;       // 0..2047
        int o   = idx >> 4;             // 0..127
        int kq  = idx & 15;             // 0..15
        float4 w = reinterpret_cast<const float4*>(We)[idx];
        Wsh[kq * 4 + 0][o] = w.x;
        Wsh[kq * 4 + 1][o] = w.y;
        Wsh[kq * 4 + 2][o] = w.z;
        Wsh[kq * 4 + 3][o] = w.w;
    }

    // Stage fill: 64 edges x 16 k = 256 float4s -> 1 per thread.
    const int le = tid >> 2;     // 0..63 (edge within tile)
    const int kq = tid & 3;      // 0..3  (float4 within 16-k stage)

    const int ntiles = (NTILES_TOT - bid + EGRID - 1) / EGRID;   // 21 or 22
    const int NS     = 4 * ntiles;

    // Prefetch + fill stage 0 of tile 0 (tile index = bid) into buffer 0.
    float4 pf = *reinterpret_cast<const float4*>(
        e + (size_t)(bid * ETILE + le) * EDGE_DIM + kq * 4);
    Esh[0][kq * 4 + 0][le] = pf.x;
    Esh[0][kq * 4 + 1][le] = pf.y;
    Esh[0][kq * 4 + 2][le] = pf.z;
    Esh[0][kq * 4 + 3][le] = pf.w;
    __syncthreads();

    u64 acc[4][4];

#pragma unroll 1
    for (int gs = 0; gs < NS; ++gs) {
        const int cur = gs & 1;
        const int it  = gs >> 2;
        const int s   = gs & 3;

        // prefetch next stage (possibly next tile's stage 0, stride EGRID)
        if (gs + 1 < NS) {
            const int nit = (gs + 1) >> 2, nss = (gs + 1) & 3;
            const int nt  = bid + nit * EGRID;
            pf = *reinterpret_cast<const float4*>(
                e + (size_t)(nt * ETILE + le) * EDGE_DIM + nss * 16 + kq * 4);
        }

        if (s == 0) {
#pragma unroll
            for (int i = 0; i < 4; ++i)
#pragma unroll
                for (int j = 0; j < 4; ++j) acc[i][j] = 0ULL;
        }

        // ---- 16 k-steps: per k = 3 LDS.128 + 4 movs + 16 fma2 ----
#pragma unroll
        for (int k = 0; k < 16; ++k) {
            const int kk = s * 16 + k;
            ulonglong2 wa = *reinterpret_cast<const ulonglong2*>(&Wsh[kk][tx * 4]);
            ulonglong2 wb = *reinterpret_cast<const ulonglong2*>(&Wsh[kk][64 + tx * 4]);
            float4 evf = *reinterpret_cast<const float4*>(&Esh[cur][k][ty * 4]);
            u64 ed[4];
            ed[0] = pack2(evf.x, evf.x);
            ed[1] = pack2(evf.y, evf.y);
            ed[2] = pack2(evf.z, evf.z);
            ed[3] = pack2(evf.w, evf.w);
#pragma unroll
            for (int i = 0; i < 4; ++i) {
                fma2(acc[i][0], ed[i], wa.x);
                fma2(acc[i][1], ed[i], wa.y);
                fma2(acc[i][2], ed[i], wb.x);
                fma2(acc[i][3], ed[i], wb.y);
            }
        }

        // ---- tile finished: gather + store epilogue ----
        if (s == 3) {
            const int t   = bid + it * EGRID;
            const int eb0 = t * ETILE + ty * 4;
#pragma unroll
            for (int i = 0; i < 4; ++i) {
                const int ea = eb0 + i;
                const int sa = fetch_idx(ei32, is64, (size_t)ea);
                const int ta = fetch_idx(ei32, is64, (size_t)N_EDGES + ea);

                const float* hu = g_HU + (size_t)sa * OUT_DIM;
                const float* hw = g_HW + (size_t)ta * OUT_DIM;
                float*       op = out + (size_t)ea * OUT_DIM;

                float4 A0 = *reinterpret_cast<const float4*>(hu + tx * 4);
                float4 B0 = *reinterpret_cast<const float4*>(hw + tx * 4);
                float2 p0 = unpack2(acc[i][0]);
                float2 p1 = unpack2(acc[i][1]);
                *reinterpret_cast<float4*>(op + tx * 4) =
                    make_float4(p0.x + A0.x + B0.x, p0.y + A0.y + B0.y,
                                p1.x + A0.z + B0.z, p1.y + A0.w + B0.w);

                float4 A1 = *reinterpret_cast<const float4*>(hu + 64 + tx * 4);
                float4 B1 = *reinterpret_cast<const float4*>(hw + 64 + tx * 4);
                float2 p2 = unpack2(acc[i][2]);
                float2 p3 = unpack2(acc[i][3]);
                *reinterpret_cast<float4*>(op + 64 + tx * 4) =
                    make_float4(p2.x + A1.x + B1.x, p2.y + A1.y + B1.y,
                                p3.x + A1.z + B1.z, p3.y + A1.w + B1.w);
            }
        }

        // ---- publish prefetched stage into the other buffer ----
        if (gs + 1 < NS) {
            const int nxt = cur ^ 1;
            Esh[nxt][kq * 4 + 0][le] = pf.x;
            Esh[nxt][kq * 4 + 1][le] = pf.y;
            Esh[nxt][kq * 4 + 2][le] = pf.z;
            Esh[nxt][kq * 4 + 3][le] = pf.w;
            __syncthreads();
        }
    }
}

extern "C" void kernel_launch(void* const* d_in, const int* in_sizes, int n_in,
                              void* d_out, int out_size)
{
    const float* h   = (const float*)d_in[0];       // [50000,128]
    const float* e   = (const float*)d_in[1];       // [800000,64]
    const int*   ei  = (const int*)d_in[2];         // [2,800000]
    const float* We  = (const float*)d_in[3];       // [128,64]
    const float* Whu = (const float*)d_in[4];       // [128,128]
    const float* Whw = (const float*)d_in[5];       // [128,128]
    float*       out = (float*)d_out;               // [800000,128]

    dim3 ngrid((N_NODES + 127) / 128, 2);
    node_proj_kernel<<<ngrid, 256>>>(h, Whu, Whw, ei);

    edge_kernel<<<EGRID, 256>>>(e, ei, We, out);
}

// round 14
// speedup vs baseline: 1.6401x; 1.1282x over previous
#include <cuda_runtime.h>
#include <cstdint>

#define N_NODES 50000
#define N_EDGES 800000
#define IN_DIM  128
#define OUT_DIM 128
#define EDGE_DIM 64

#define ETILE      64                    // edges per tile
#define NTILES_TOT 12500                 // 800000 / 64
#define EGRID      444                   // 148 SMs * occ 3 -> single wave

typedef unsigned long long u64;

// Scratch for node projections (allocation-free per harness rules).
__device__ __align__(16) float g_HU[(size_t)N_NODES * OUT_DIM];
__device__ __align__(16) float g_HW[(size_t)N_NODES * OUT_DIM];
__device__ int g_idx_is64;

__device__ __forceinline__ u64 pack2(float lo, float hi) {
    u64 r; asm("mov.b64 %0, {%1, %2};" : "=l"(r) : "f"(lo), "f"(hi)); return r;
}
__device__ __forceinline__ void fma2(u64& d, u64 a, u64 b) {
    asm("fma.rn.f32x2 %0, %1, %2, %3;" : "=l"(d) : "l"(a), "l"(b), "l"(d));
}
__device__ __forceinline__ float2 unpack2(u64 v) {
    float2 f; asm("mov.b64 {%0, %1}, %2;" : "=f"(f.x), "=f"(f.y) : "l"(v)); return f;
}
__device__ __forceinline__ int fetch_idx(const int* __restrict__ ei32,
                                         int is64, size_t pos) {
    int v = is64 ? ei32[2 * pos] : ei32[pos];
    v = v < 0 ? 0 : (v >= N_NODES ? N_NODES - 1 : v);
    return v;
}

// ---------------------------------------------------------------------------
// Node projection (both W_hu and W_hw via blockIdx.y) — proven kernel.
// Block (0,0) also performs index-dtype detection (edge launches after).
// ---------------------------------------------------------------------------
__global__ __launch_bounds__(256, 2)
void node_proj_kernel(const float* __restrict__ h,
                      const float* __restrict__ Whu,
                      const float* __restrict__ Whw,
                      const int* __restrict__ ei32)
{
    __shared__ __align__(16) float Wsh[32][132];
    __shared__ __align__(16) float Hsh[32][132];

    if (blockIdx.x == 0 && blockIdx.y == 0 && threadIdx.x == 0) {
        int all_zero = 1;
        for (int i = 0; i < 256; ++i)
            if (ei32[2 * i + 1] != 0) { all_zero = 0; break; }
        g_idx_is64 = all_zero;
    }

    const float* __restrict__ W   = blockIdx.y ? Whw : Whu;
    float*       __restrict__ dst = blockIdx.y ? g_HW : g_HU;

    const int tid = threadIdx.x;
    const int tx  = tid & 31;
    const int ty  = tid >> 5;
    const int n0  = blockIdx.x * 128;

    u64 acc[8][4];
#pragma unroll
    for (int p = 0; p < 8; ++p)
#pragma unroll
        for (int j = 0; j < 4; ++j) acc[p][j] = 0ULL;

#pragma unroll 1
    for (int s = 0; s < 4; ++s) {
        __syncthreads();
#pragma unroll
        for (int it = 0; it < 4; ++it) {
            int idx = it * 256 + tid;
            int o   = idx >> 3;
            int kq  = idx & 7;
            float4 w = *reinterpret_cast<const float4*>(W + (size_t)o * IN_DIM + s * 32 + kq * 4);
            Wsh[kq * 4 + 0][o] = w.x; Wsh[kq * 4 + 1][o] = w.y;
            Wsh[kq * 4 + 2][o] = w.z; Wsh[kq * 4 + 3][o] = w.w;
        }
#pragma unroll
        for (int it = 0; it < 4; ++it) {
            int idx = it * 256 + tid;
            int ln  = idx >> 3;
            int kq  = idx & 7;
            int n   = n0 + ln;
            float4 v = make_float4(0.f, 0.f, 0.f, 0.f);
            if (n < N_NODES)
                v = *reinterpret_cast<const float4*>(h + (size_t)n * IN_DIM + s * 32 + kq * 4);
            Hsh[kq * 4 + 0][ln] = v.x; Hsh[kq * 4 + 1][ln] = v.y;
            Hsh[kq * 4 + 2][ln] = v.z; Hsh[kq * 4 + 3][ln] = v.w;
        }
        __syncthreads();

#pragma unroll
        for (int k = 0; k < 32; ++k) {
            float4 w = *reinterpret_cast<const float4*>(&Wsh[k][tx * 4]);
            u64 w2[4];
            w2[0] = pack2(w.x, w.x); w2[1] = pack2(w.y, w.y);
            w2[2] = pack2(w.z, w.z); w2[3] = pack2(w.w, w.w);
            u64 ev[8];
#pragma unroll
            for (int q = 0; q < 4; ++q) {
                ulonglong2 ep = *reinterpret_cast<const ulonglong2*>(&Hsh[k][ty * 16 + q * 4]);
                ev[2 * q] = ep.x; ev[2 * q + 1] = ep.y;
            }
#pragma unroll
            for (int p = 0; p < 8; ++p)
#pragma unroll
                for (int j = 0; j < 4; ++j)
                    fma2(acc[p][j], ev[p], w2[j]);
        }
    }

#pragma unroll
    for (int p = 0; p < 8; ++p) {
        int na = n0 + ty * 16 + 2 * p;
        float2 v0 = unpack2(acc[p][0]), v1 = unpack2(acc[p][1]);
        float2 v2 = unpack2(acc[p][2]), v3 = unpack2(acc[p][3]);
        if (na < N_NODES)
            *reinterpret_cast<float4*>(dst + (size_t)na * OUT_DIM + tx * 4) =
                make_float4(v0.x, v1.x, v2.x, v3.x);
        if (na + 1 < N_NODES)
            *reinterpret_cast<float4*>(dst + (size_t)(na + 1) * OUT_DIM + tx * 4) =
                make_float4(v0.y, v1.y, v2.y, v3.y);
    }
}

// ---------------------------------------------------------------------------
// Fused edge kernel v9: distinct-byte LDS mapping.
//   lane (0..31) = out-quad over FULL 128 outs -> W LDS.128 512B distinct (4wf)
//   warp (0..7)  = 8-edge group -> E reads are whole-warp broadcasts (1wf)
//   Thread tile: 4 edge-pairs x 4 outs, 16 u64 accs.
//   Block tile: 64 edges x 128 outs; stage=16k double-buffered, 1 barrier/stage.
//   Persistent single wave: grid 444, tiles strided by 444. Occupancy 3.
// ---------------------------------------------------------------------------
__global__ __launch_bounds__(256, 3)
void edge_kernel(const float* __restrict__ e,
                 const int* __restrict__ ei32,
                 const float* __restrict__ We,
                 float* __restrict__ out)
{
    __shared__ __align__(16) float Wsh[EDGE_DIM][132];   // [k][o]      33.8 KB
    __shared__ __align__(16) float Esh[2][16][68];       // [buf][k][e]  8.7 KB

    const int tid  = threadIdx.x;
    const int lane = tid & 31;   // out-quad: lane*4 .. +3
    const int wy   = tid >> 5;   // edge group: wy*8 .. wy*8+7
    const int bid  = blockIdx.x;
    const int is64 = g_idx_is64;

    // One-time W fill: We[o][kq*4..] -> Wsh[kq*4+j][o], 2048 float4s.
#pragma unroll
    for (int it = 0; it < 8; ++it) {
        int idx = it * 256 + tid;       // 0..2047
        int o   = idx >> 4;             // 0..127
        int kq  = idx & 15;             // 0..15
        float4 w = reinterpret_cast<const float4*>(We)[idx];
        Wsh[kq * 4 + 0][o] = w.x;
        Wsh[kq * 4 + 1][o] = w.y;
        Wsh[kq * 4 + 2][o] = w.z;
        Wsh[kq * 4 + 3][o] = w.w;
    }

    // Stage fill: 64 edges x 16 k = 256 float4 -> 1 per thread.
    const int le = tid >> 2;     // edge within tile 0..63
    const int kq = tid & 3;      // float4 within stage 0..3

    const int ntiles = (NTILES_TOT - bid + EGRID - 1) / EGRID;   // 28 or 29
    const int NS     = 4 * ntiles;

    // Prologue: stage 0 of tile bid into buffer 0.
    float4 pf = *reinterpret_cast<const float4*>(
        e + (size_t)(bid * ETILE + le) * EDGE_DIM + kq * 4);
    Esh[0][kq * 4 + 0][le] = pf.x;
    Esh[0][kq * 4 + 1][le] = pf.y;
    Esh[0][kq * 4 + 2][le] = pf.z;
    Esh[0][kq * 4 + 3][le] = pf.w;
    __syncthreads();

    u64 acc[4][4];

#pragma unroll 1
    for (int gs = 0; gs < NS; ++gs) {
        const int cur = gs & 1;
        const int it  = gs >> 2;
        const int s   = gs & 3;

        // prefetch next stage (possibly next tile's stage 0, stride EGRID)
        if (gs + 1 < NS) {
            const int nit = (gs + 1) >> 2, nss = (gs + 1) & 3;
            const int nt  = bid + nit * EGRID;
            pf = *reinterpret_cast<const float4*>(
                e + (size_t)(nt * ETILE + le) * EDGE_DIM + nss * 16 + kq * 4);
        }

        if (s == 0) {
#pragma unroll
            for (int p = 0; p < 4; ++p)
#pragma unroll
                for (int j = 0; j < 4; ++j) acc[p][j] = 0ULL;
        }

        // ---- 16 k-steps: 1 W LDS.128 (distinct) + 2 E LDS.128 (broadcast)
        //      + 4 dup movs + 16 fma2 ----
#pragma unroll
        for (int k = 0; k < 16; ++k) {
            const int kk = s * 16 + k;
            float4 w = *reinterpret_cast<const float4*>(&Wsh[kk][lane * 4]);
            u64 w2[4];
            w2[0] = pack2(w.x, w.x); w2[1] = pack2(w.y, w.y);
            w2[2] = pack2(w.z, w.z); w2[3] = pack2(w.w, w.w);
            u64 ev[4];
            {
                ulonglong2 ea = *reinterpret_cast<const ulonglong2*>(&Esh[cur][k][wy * 8]);
                ulonglong2 eb = *reinterpret_cast<const ulonglong2*>(&Esh[cur][k][wy * 8 + 4]);
                ev[0] = ea.x; ev[1] = ea.y; ev[2] = eb.x; ev[3] = eb.y;
            }
#pragma unroll
            for (int p = 0; p < 4; ++p)
#pragma unroll
                for (int j = 0; j < 4; ++j)
                    fma2(acc[p][j], ev[p], w2[j]);
        }

        // ---- tile finished: gather + store epilogue ----
        if (s == 3) {
            const int t    = bid + it * EGRID;
            const int base = t * ETILE + wy * 8;     // warp's 8 edges
            // all 16 index loads issued before first use (MLP)
            int sidx[8], tidx[8];
#pragma unroll
            for (int i = 0; i < 8; ++i) {
                sidx[i] = fetch_idx(ei32, is64, (size_t)(base + i));
                tidx[i] = fetch_idx(ei32, is64, (size_t)N_EDGES + base + i);
            }
#pragma unroll
            for (int p = 0; p < 4; ++p) {
                const int ea = base + 2 * p;
                float2 v0 = unpack2(acc[p][0]), v1 = unpack2(acc[p][1]);
                float2 v2 = unpack2(acc[p][2]), v3 = unpack2(acc[p][3]);

                float4 A = *reinterpret_cast<const float4*>(
                    g_HU + (size_t)sidx[2 * p] * OUT_DIM + lane * 4);
                float4 B = *reinterpret_cast<const float4*>(
                    g_HW + (size_t)tidx[2 * p] * OUT_DIM + lane * 4);
                float4 C = *reinterpret_cast<const float4*>(
                    g_HU + (size_t)sidx[2 * p + 1] * OUT_DIM + lane * 4);
                float4 D = *reinterpret_cast<const float4*>(
                    g_HW + (size_t)tidx[2 * p + 1] * OUT_DIM + lane * 4);

                *reinterpret_cast<float4*>(out + (size_t)ea * OUT_DIM + lane * 4) =
                    make_float4(v0.x + A.x + B.x, v1.x + A.y + B.y,
                                v2.x + A.z + B.z, v3.x + A.w + B.w);
                *reinterpret_cast<float4*>(out + (size_t)(ea + 1) * OUT_DIM + lane * 4) =
                    make_float4(v0.y + C.x + D.x, v1.y + C.y + D.y,
                                v2.y + C.z + D.z, v3.y + C.w + D.w);
            }
        }

        // ---- publish prefetched stage into the other buffer ----
        if (gs + 1 < NS) {
            const int nxt = cur ^ 1;
            Esh[nxt][kq * 4 + 0][le] = pf.x;
            Esh[nxt][kq * 4 + 1][le] = pf.y;
            Esh[nxt][kq * 4 + 2][le] = pf.z;
            Esh[nxt][kq * 4 + 3][le] = pf.w;
            __syncthreads();
        }
    }
}

extern "C" void kernel_launch(void* const* d_in, const int* in_sizes, int n_in,
                              void* d_out, int out_size)
{
    const float* h   = (const float*)d_in[0];       // [50000,128]
    const float* e   = (const float*)d_in[1];       // [800000,64]
    const int*   ei  = (const int*)d_in[2];         // [2,800000]
    const float* We  = (const float*)d_in[3];       // [128,64]
    const float* Whu = (const float*)d_in[4];       // [128,128]
    const float* Whw = (const float*)d_in[5];       // [128,128]
    float*       out = (float*)d_out;               // [800000,128]

    dim3 ngrid((N_NODES + 127) / 128, 2);
    node_proj_kernel<<<ngrid, 256>>>(h, Whu, Whw, ei);

    edge_kernel<<<EGRID, 256>>>(e, ei, We, out);
}